// round 9
// baseline (speedup 1.0000x reference)
#include <cuda_runtime.h>
#include <math_constants.h>
#include <cstdint>

// Problem constants
#define BATCH   64
#define SEQL    256
#define EDIM    512
#define SDIM    1024
#define KDIM    1024   // 2*E
#define NCLASS  2

// GEMM tile config (int8 mma.sync m16n8k32 + ldmatrix)
#define BM 128
#define BN 128
#define BKB 128                    // k-bytes per k-tile
#define LDTB 144                   // padded smem row stride in bytes
#define TILE_BYTES (128 * LDTB)    // 18432
#define STAGE_BYTES (2 * TILE_BYTES)         // A + B = 36864
#define SMEM_BYTES  (2 * STAGE_BYTES)        // 2 stages = 73728
#define NKT (KDIM / BKB)           // 8

// Scratch (static device globals)
__device__ float  g_embf[BATCH * SEQL * EDIM];   // gathered f32 embeddings
__device__ float  g_rowmax[BATCH * SEQL];        // per emb-row absmax
__device__ int8_t g_qa[BATCH * SEQL * KDIM];     // quantized pair rows
__device__ int8_t g_qb[SDIM * KDIM];             // quantized Wc
__device__ float  g_sA[BATCH * SEQL];            // pair-row scales
__device__ float  g_sB[SDIM];                    // Wc row scales
__device__ float  g_sentpre[BATCH * SDIM];
__device__ float  g_h[BATCH * 64];

__device__ __forceinline__ void atomicMaxFloat(float* addr, float val) {
    if (val >= 0.0f) atomicMax(reinterpret_cast<int*>(addr), __float_as_int(val));
    else             atomicMin(reinterpret_cast<unsigned int*>(addr), __float_as_uint(val));
}

__device__ __forceinline__ void mma_s8(int c[4], const uint32_t a[4],
                                       uint32_t b0, uint32_t b1) {
    asm volatile(
        "mma.sync.aligned.m16n8k32.row.col.s32.s8.s8.s32 "
        "{%0,%1,%2,%3}, {%4,%5,%6,%7}, {%8,%9}, {%0,%1,%2,%3};"
        : "+r"(c[0]), "+r"(c[1]), "+r"(c[2]), "+r"(c[3])
        : "r"(a[0]), "r"(a[1]), "r"(a[2]), "r"(a[3]), "r"(b0), "r"(b1));
}

__device__ __forceinline__ void ldmatrix_x4(uint32_t r[4], uint32_t addr) {
    asm volatile("ldmatrix.sync.aligned.m8n8.x4.shared.b16 {%0,%1,%2,%3}, [%4];"
                 : "=r"(r[0]), "=r"(r[1]), "=r"(r[2]), "=r"(r[3]) : "r"(addr));
}

__device__ __forceinline__ void cp_async16(uint32_t saddr, const void* gptr, bool pred) {
    int sz = pred ? 16 : 0;
    asm volatile("cp.async.cg.shared.global [%0], [%1], 16, %2;"
                 :: "r"(saddr), "l"(gptr), "r"(sz));
}

__device__ __forceinline__ int8_t quant1(float x, float inv) {
    int q = __float2int_rn(x * inv);
    q = max(-127, min(127, q));
    return (int8_t)q;
}

// ---------------------------------------------------------------------------
// Kernel 1a: embedding gather (f32) + per-row absmax
// ---------------------------------------------------------------------------
__global__ __launch_bounds__(128) void gather_kernel(const int* __restrict__ inputs,
                                                     const float* __restrict__ emb_table) {
    int row = blockIdx.x;
    int tok = inputs[row];
    float4 v = reinterpret_cast<const float4*>(emb_table + (size_t)tok * EDIM)[threadIdx.x];
    reinterpret_cast<float4*>(g_embf + (size_t)row * EDIM)[threadIdx.x] = v;

    float m = fmaxf(fmaxf(fabsf(v.x), fabsf(v.y)), fmaxf(fabsf(v.z), fabsf(v.w)));
#pragma unroll
    for (int o = 16; o > 0; o >>= 1) m = fmaxf(m, __shfl_xor_sync(0xffffffffu, m, o));
    __shared__ float red[4];
    if ((threadIdx.x & 31) == 0) red[threadIdx.x >> 5] = m;
    __syncthreads();
    if (threadIdx.x == 0)
        g_rowmax[row] = fmaxf(fmaxf(red[0], red[1]), fmaxf(red[2], red[3]));
}

// ---------------------------------------------------------------------------
// Kernel 1b: pair-row quantization.  Block = (b,l): row l = [emb_l, emb_{l+1}]
// quantized with one scale; sA[row] = scale/127.
// ---------------------------------------------------------------------------
__global__ __launch_bounds__(128) void pairquant_kernel() {
    int row = blockIdx.x;               // b*256 + l
    int l   = row & (SEQL - 1);
    if (l >= SEQL - 1) { if (threadIdx.x == 0) g_sA[row] = 0.0f; return; }

    float mx  = fmaxf(g_rowmax[row], g_rowmax[row + 1]);
    float inv = (mx > 0.0f) ? 127.0f / mx : 0.0f;
    if (threadIdx.x == 0) g_sA[row] = (mx > 0.0f) ? mx / 127.0f : 0.0f;

    const float4* h0 = reinterpret_cast<const float4*>(g_embf + (size_t)row * EDIM);
    const float4* h1 = reinterpret_cast<const float4*>(g_embf + (size_t)(row + 1) * EDIM);
    char4* dst = reinterpret_cast<char4*>(g_qa + (size_t)row * KDIM);

    float4 a = h0[threadIdx.x];
    dst[threadIdx.x] = make_char4(quant1(a.x, inv), quant1(a.y, inv),
                                  quant1(a.z, inv), quant1(a.w, inv));
    float4 b = h1[threadIdx.x];
    dst[128 + threadIdx.x] = make_char4(quant1(b.x, inv), quant1(b.y, inv),
                                        quant1(b.z, inv), quant1(b.w, inv));
}

// ---------------------------------------------------------------------------
// Kernel 1c: Wc per-row quantization (1024 rows of 1024).
// ---------------------------------------------------------------------------
__global__ __launch_bounds__(256) void wcquant_kernel(const float* __restrict__ Wc) {
    int s = blockIdx.x;
    const float4* src = reinterpret_cast<const float4*>(Wc + (size_t)s * KDIM);
    float4 v = src[threadIdx.x];
    float m = fmaxf(fmaxf(fabsf(v.x), fabsf(v.y)), fmaxf(fabsf(v.z), fabsf(v.w)));
#pragma unroll
    for (int o = 16; o > 0; o >>= 1) m = fmaxf(m, __shfl_xor_sync(0xffffffffu, m, o));
    __shared__ float red[8];
    if ((threadIdx.x & 31) == 0) red[threadIdx.x >> 5] = m;
    __syncthreads();
    if (threadIdx.x < 8) {
        float t = red[threadIdx.x];
#pragma unroll
        for (int o = 4; o > 0; o >>= 1) t = fmaxf(t, __shfl_xor_sync(0xffu, t, o));
        if (threadIdx.x == 0) red[0] = t;
    }
    __syncthreads();
    float mx  = red[0];
    float inv = (mx > 0.0f) ? 127.0f / mx : 0.0f;
    if (threadIdx.x == 0) g_sB[s] = (mx > 0.0f) ? mx / 127.0f : 0.0f;
    reinterpret_cast<char4*>(g_qb + (size_t)s * KDIM)[threadIdx.x] =
        make_char4(quant1(v.x, inv), quant1(v.y, inv), quant1(v.z, inv), quant1(v.w, inv));
}

// ---------------------------------------------------------------------------
// Kernel 2: init max accumulator
// ---------------------------------------------------------------------------
__global__ void init_kernel() {
    int i = blockIdx.x * blockDim.x + threadIdx.x;
    if (i < BATCH * SDIM) g_sentpre[i] = -CUDART_INF_F;
}

// ---------------------------------------------------------------------------
// Kernel 3: INT8 tensor-core conv GEMM + fused dequant + max-pool.
// Block: 256 threads = 8 warps (2m x 4n), warp tile 64x32, ldmatrix fragments.
// Grid: (8 ntiles, 2 mtiles, 64 batches). 2-stage cp.async pipeline, NKT=8.
// ---------------------------------------------------------------------------
__global__ __launch_bounds__(256, 2) void conv_max_kernel(const float* __restrict__ bc)
{
    extern __shared__ int8_t sm[];

    const int b    = blockIdx.z;
    const int m0   = blockIdx.y * BM;
    const int n0   = blockIdx.x * BN;
    const int tid  = threadIdx.x;
    const int lane = tid & 31;
    const int warp = tid >> 5;
    const int wm   = warp >> 2;        // 0..1
    const int wn   = warp & 3;         // 0..3
    const int g    = lane >> 2;        // 0..7
    const int t    = lane & 3;         // 0..3

    const int8_t* Ag = g_qa + ((size_t)b * SEQL + m0) * KDIM;
    const int8_t* Bg = g_qb + (size_t)n0 * KDIM;

    const uint32_t smem_u32 = (uint32_t)__cvta_generic_to_shared(sm);
    const uint32_t lm_row = (uint32_t)(lane & 15) * LDTB;
    const uint32_t lm_col = (uint32_t)(lane >> 4) * 16;

    auto load_tile = [&](int kt, int st) {
        uint32_t base = smem_u32 + (uint32_t)st * STAGE_BYTES;
#pragma unroll
        for (int i = 0; i < 8; i++) {
            int c   = tid + 256 * i;            // 0..2047
            int row = (c & 1023) >> 3;          // 0..127
            int ch  = c & 7;                    // 16B chunk within 128B of k
            uint32_t daddr = base + (c < 1024 ? 0u : (uint32_t)TILE_BYTES)
                           + (uint32_t)(row * LDTB + ch * 16);
            if (c < 1024) {
                bool av = (m0 + row) < (SEQL - 1);
                cp_async16(daddr, Ag + (size_t)row * KDIM + kt * BKB + ch * 16, av);
            } else {
                cp_async16(daddr, Bg + (size_t)row * KDIM + kt * BKB + ch * 16, true);
            }
        }
    };

    int acc[4][4][4];
#pragma unroll
    for (int mt = 0; mt < 4; mt++)
#pragma unroll
        for (int nt = 0; nt < 4; nt++)
#pragma unroll
            for (int q = 0; q < 4; q++) acc[mt][nt][q] = 0;

    load_tile(0, 0);
    asm volatile("cp.async.commit_group;");

    for (int kt = 0; kt < NKT; ++kt) {
        if (kt + 1 < NKT) {
            load_tile(kt + 1, (kt + 1) & 1);
            asm volatile("cp.async.commit_group;");
            asm volatile("cp.async.wait_group 1;");
        } else {
            asm volatile("cp.async.wait_group 0;");
        }
        __syncthreads();

        const uint32_t abase = smem_u32 + (uint32_t)(kt & 1) * STAGE_BYTES;
        const uint32_t bbase = abase + TILE_BYTES;

#pragma unroll
        for (int ks = 0; ks < 4; ks++) {       // 4 ksteps of k32 bytes per BKB=128
            const uint32_t kb = (uint32_t)ks * 32 + lm_col;
            uint32_t af[4][4];
#pragma unroll
            for (int mt = 0; mt < 4; mt++)
                ldmatrix_x4(af[mt],
                    abase + (uint32_t)(wm * 64 + mt * 16) * LDTB + lm_row + kb);
            uint32_t bq[2][4];
#pragma unroll
            for (int bn = 0; bn < 2; bn++)
                ldmatrix_x4(bq[bn],
                    bbase + (uint32_t)(wn * 32 + bn * 16) * LDTB + lm_row + kb);
#pragma unroll
            for (int mt = 0; mt < 4; mt++)
#pragma unroll
                for (int nt = 0; nt < 4; nt++) {
                    const int bn = nt >> 1, sel = nt & 1;
                    mma_s8(acc[mt][nt], af[mt], bq[bn][sel], bq[bn][sel + 2]);
                }
        }
        __syncthreads();
    }

    // --- epilogue: dequant (sA per row, sB per col), max over rows ---
    float sB2[4][2];
#pragma unroll
    for (int nt = 0; nt < 4; nt++)
#pragma unroll
        for (int j = 0; j < 2; j++)
            sB2[nt][j] = __ldg(&g_sB[n0 + wn * 32 + nt * 8 + 2 * t + j]);

    float cmax[4][2];
#pragma unroll
    for (int nt = 0; nt < 4; nt++) { cmax[nt][0] = -CUDART_INF_F; cmax[nt][1] = -CUDART_INF_F; }

#pragma unroll
    for (int mt = 0; mt < 4; mt++) {
        int r0 = m0 + wm * 64 + mt * 16 + g;     // batch-local l
        bool v0 = r0 < (SEQL - 1);
        bool v1 = (r0 + 8) < (SEQL - 1);
        float sa0 = v0 ? __ldg(&g_sA[b * SEQL + r0]) : 0.0f;
        float sa1 = v1 ? __ldg(&g_sA[b * SEQL + r0 + 8]) : 0.0f;
#pragma unroll
        for (int nt = 0; nt < 4; nt++) {
            if (v0) {
                cmax[nt][0] = fmaxf(cmax[nt][0], (float)acc[mt][nt][0] * sa0 * sB2[nt][0]);
                cmax[nt][1] = fmaxf(cmax[nt][1], (float)acc[mt][nt][1] * sa0 * sB2[nt][1]);
            }
            if (v1) {
                cmax[nt][0] = fmaxf(cmax[nt][0], (float)acc[mt][nt][2] * sa1 * sB2[nt][0]);
                cmax[nt][1] = fmaxf(cmax[nt][1], (float)acc[mt][nt][3] * sa1 * sB2[nt][1]);
            }
        }
    }
#pragma unroll
    for (int nt = 0; nt < 4; nt++)
#pragma unroll
        for (int j = 0; j < 2; j++) {
            float v = cmax[nt][j];
            v = fmaxf(v, __shfl_xor_sync(0xffffffffu, v, 4));
            v = fmaxf(v, __shfl_xor_sync(0xffffffffu, v, 8));
            v = fmaxf(v, __shfl_xor_sync(0xffffffffu, v, 16));
            cmax[nt][j] = v;
        }
    if (g == 0) {
#pragma unroll
        for (int nt = 0; nt < 4; nt++)
#pragma unroll
            for (int j = 0; j < 2; j++) {
                int col = n0 + wn * 32 + nt * 8 + 2 * t + j;
                atomicMaxFloat(&g_sentpre[(size_t)b * SDIM + col],
                               cmax[nt][j] + __ldg(&bc[col]));
            }
    }
}

// ---------------------------------------------------------------------------
// Kernel 4a: h[b][j] = dot(sigmoid(sentpre[b]), W1[j]) + b1[j]
// ---------------------------------------------------------------------------
__global__ __launch_bounds__(256) void h_kernel(
    const float* __restrict__ W1, const float* __restrict__ b1)
{
    const int b = blockIdx.x;
    __shared__ float sent[SDIM];
    for (int i = threadIdx.x; i < SDIM; i += 256) {
        float v = g_sentpre[(size_t)b * SDIM + i];
        sent[i] = 1.0f / (1.0f + expf(-v));
    }
    __syncthreads();

    const int w    = threadIdx.x >> 5;
    const int lane = threadIdx.x & 31;
    for (int j = w; j < 50; j += 8) {
        const float4* wrow = reinterpret_cast<const float4*>(W1 + (size_t)j * SDIM);
        float sum = 0.0f;
#pragma unroll
        for (int i = lane; i < SDIM / 4; i += 32) {
            float4 v = wrow[i];
            const float* s = &sent[i * 4];
            sum = fmaf(v.x, s[0], sum);
            sum = fmaf(v.y, s[1], sum);
            sum = fmaf(v.z, s[2], sum);
            sum = fmaf(v.w, s[3], sum);
        }
#pragma unroll
        for (int o = 16; o > 0; o >>= 1) sum += __shfl_down_sync(0xffffffffu, sum, o);
        if (lane == 0) g_h[b * 64 + j] = sum + b1[j];
    }
}

// ---------------------------------------------------------------------------
// Kernel 4b: logits + log_softmax
// ---------------------------------------------------------------------------
__global__ void out_kernel(const float* __restrict__ W2, const float* __restrict__ b2,
                           float* __restrict__ out)
{
    int b = threadIdx.x;
    if (b >= BATCH) return;
    float l0 = b2[0], l1 = b2[1];
#pragma unroll
    for (int j = 0; j < 50; j++) {
        float h = g_h[b * 64 + j];
        l0 = fmaf(h, W2[j], l0);
        l1 = fmaf(h, W2[50 + j], l1);
    }
    float m   = fmaxf(l0, l1);
    float lse = m + logf(expf(l0 - m) + expf(l1 - m));
    out[b * NCLASS + 0] = l0 - lse;
    out[b * NCLASS + 1] = l1 - lse;
}

// ---------------------------------------------------------------------------
// kernel_launch
// inputs order: inputs(int32), emb_table, Wc, bc, W1, b1, W2, b2
// ---------------------------------------------------------------------------
extern "C" void kernel_launch(void* const* d_in, const int* in_sizes, int n_in,
                              void* d_out, int out_size) {
    const int*   inputs = (const int*)  d_in[0];
    const float* emb    = (const float*)d_in[1];
    const float* Wc     = (const float*)d_in[2];
    const float* bc     = (const float*)d_in[3];
    const float* W1     = (const float*)d_in[4];
    const float* b1     = (const float*)d_in[5];
    const float* W2     = (const float*)d_in[6];
    const float* b2     = (const float*)d_in[7];
    float* out = (float*)d_out;

    cudaFuncSetAttribute(conv_max_kernel,
                         cudaFuncAttributeMaxDynamicSharedMemorySize, SMEM_BYTES);

    gather_kernel<<<BATCH * SEQL, 128>>>(inputs, emb);
    pairquant_kernel<<<BATCH * SEQL, 128>>>();
    wcquant_kernel<<<SDIM, 256>>>(Wc);
    init_kernel<<<(BATCH * SDIM + 255) / 256, 256>>>();

    dim3 grid(SDIM / BN, (SEQL + BM - 1) / BM, BATCH);   // (8, 2, 64)
    conv_max_kernel<<<grid, 256, SMEM_BYTES>>>(bc);

    h_kernel<<<BATCH, 256>>>(W1, b1);
    out_kernel<<<1, 64>>>(W2, b2, out);
}

// round 10
// speedup vs baseline: 2.2263x; 2.2263x over previous
#include <cuda_runtime.h>
#include <cuda_bf16.h>
#include <math_constants.h>
#include <cstdint>

// Problem constants
#define BATCH   64
#define SEQL    256
#define EDIM    512
#define SDIM    1024
#define KDIM    1024   // 2*E
#define NCLASS  2

// GEMM tile config (bf16 mma.sync m16n8k16) — proven 106.5us config from R6
#define BM 128
#define BN 128
#define BK 64                      // halves per k-tile (128 bytes of bf16)
#define LDT 72                     // padded smem row stride in halves (conflict-free)
#define TILE_HALVES (128 * LDT)    // one 128xBK tile
#define TILE_BYTES  (TILE_HALVES * 2)        // 18432
#define STAGE_HALVES (2 * TILE_HALVES)
#define SMEM_BYTES (2 * STAGE_HALVES * 2)    // 2 stages * (A+B) = 73728 B
#define NKT (KDIM / BK)            // 16

// Scratch (static device globals; no allocations allowed)
__device__ __nv_bfloat16 g_embs[BATCH * SEQL * EDIM];  // gathered embeddings (bf16)
__device__ __nv_bfloat16 g_wc[SDIM * KDIM];            // bf16 Wc
__device__ float g_sentpre[BATCH * SDIM];              // pre-sigmoid max accumulator

__device__ __forceinline__ void atomicMaxFloat(float* addr, float val) {
    if (val >= 0.0f) atomicMax(reinterpret_cast<int*>(addr), __float_as_int(val));
    else             atomicMin(reinterpret_cast<unsigned int*>(addr), __float_as_uint(val));
}

__device__ __forceinline__ void mma_bf16(float c[4], const uint32_t a[4], const uint32_t b[2]) {
    asm volatile(
        "mma.sync.aligned.m16n8k16.row.col.f32.bf16.bf16.f32 "
        "{%0,%1,%2,%3}, {%4,%5,%6,%7}, {%8,%9}, {%0,%1,%2,%3};"
        : "+f"(c[0]), "+f"(c[1]), "+f"(c[2]), "+f"(c[3])
        : "r"(a[0]), "r"(a[1]), "r"(a[2]), "r"(a[3]), "r"(b[0]), "r"(b[1]));
}

__device__ __forceinline__ void cp_async16(uint32_t saddr, const void* gptr, bool pred) {
    int sz = pred ? 16 : 0;
    asm volatile("cp.async.cg.shared.global [%0], [%1], 16, %2;"
                 :: "r"(saddr), "l"(gptr), "r"(sz));
}

__device__ __forceinline__ uint32_t pack_bf16(float lo, float hi) {
    __nv_bfloat162 p = __floats2bfloat162_rn(lo, hi);
    return *reinterpret_cast<uint32_t*>(&p);
}

// ---------------------------------------------------------------------------
// Kernel 1a: embedding gather -> bf16
// ---------------------------------------------------------------------------
__global__ void gather_kernel(const int* __restrict__ inputs,
                              const float* __restrict__ emb_table) {
    int row = blockIdx.x;
    int tok = inputs[row];
    float4 v = reinterpret_cast<const float4*>(emb_table + (size_t)tok * EDIM)[threadIdx.x];
    uint2 o;
    o.x = pack_bf16(v.x, v.y);
    o.y = pack_bf16(v.z, v.w);
    reinterpret_cast<uint2*>(g_embs + (size_t)row * EDIM)[threadIdx.x] = o;
}

// ---------------------------------------------------------------------------
// Kernel 1b: Wc -> bf16, plus g_sentpre init folded in (runs before GEMM).
// Grid 1024 x 256 threads. Each block also initializes 64 sentpre entries.
// ---------------------------------------------------------------------------
__global__ void wc_round_kernel(const float* __restrict__ Wc) {
    int i = blockIdx.x * blockDim.x + threadIdx.x;   // float4 index
    float4 v = reinterpret_cast<const float4*>(Wc)[i];
    uint2 o;
    o.x = pack_bf16(v.x, v.y);
    o.y = pack_bf16(v.z, v.w);
    reinterpret_cast<uint2*>(g_wc)[i] = o;

    if (threadIdx.x < 64)
        g_sentpre[blockIdx.x * 64 + threadIdx.x] = -CUDART_INF_F;
}

// ---------------------------------------------------------------------------
// Kernel 2: BF16 tensor-core conv GEMM + fused max-pool (identical to R6 best).
// Block: 128 threads = 4 warps (2x2), warp tile 64x64, mma m16n8k16.
// Grid: (8 ntiles, 2 mtiles, 64 batches). 2-stage cp.async pipeline.
// ---------------------------------------------------------------------------
__global__ __launch_bounds__(128, 2) void conv_max_kernel(const float* __restrict__ bc)
{
    extern __shared__ __nv_bfloat16 sm[];

    const int b   = blockIdx.z;
    const int m0  = blockIdx.y * BM;
    const int n0  = blockIdx.x * BN;
    const int tid = threadIdx.x;
    const int lane = tid & 31;
    const int warp = tid >> 5;
    const int wm = warp >> 1;         // 0..1
    const int wn = warp & 1;          // 0..1
    const int g  = lane >> 2;         // 0..7
    const int t  = lane & 3;          // 0..3

    const __nv_bfloat16* Ag = g_embs + (size_t)b * SEQL * EDIM + (size_t)m0 * EDIM;
    const __nv_bfloat16* Bg = g_wc + (size_t)n0 * KDIM;

    const uint32_t smem_u32 = (uint32_t)__cvta_generic_to_shared(sm);

    // --- tile loader: stage st <- k-tile kt ---
    auto load_tile = [&](int kt, int st) {
        uint32_t base = smem_u32 + (uint32_t)st * (STAGE_HALVES * 2);
#pragma unroll
        for (int i = 0; i < 16; i++) {
            int c   = tid + 128 * i;            // 0..2047
            int row = (c & 1023) >> 3;          // 0..127
            int ch  = c & 7;                    // 16B chunk within 128B of k
            uint32_t daddr = base + (c < 1024 ? 0u : (uint32_t)TILE_BYTES)
                           + (uint32_t)(row * LDT * 2 + ch * 16);
            if (c < 1024) {
                bool av = (m0 + row) < (SEQL - 1);
                cp_async16(daddr, Ag + (size_t)row * EDIM + kt * BK + ch * 8, av);
            } else {
                cp_async16(daddr, Bg + (size_t)row * KDIM + kt * BK + ch * 8, true);
            }
        }
    };

    float acc[4][8][4];
#pragma unroll
    for (int mt = 0; mt < 4; mt++)
#pragma unroll
        for (int nt = 0; nt < 8; nt++)
#pragma unroll
            for (int q = 0; q < 4; q++) acc[mt][nt][q] = 0.0f;

    load_tile(0, 0);
    asm volatile("cp.async.commit_group;");

    for (int kt = 0; kt < NKT; ++kt) {
        if (kt + 1 < NKT) {
            load_tile(kt + 1, (kt + 1) & 1);
            asm volatile("cp.async.commit_group;");
            asm volatile("cp.async.wait_group 1;");
        } else {
            asm volatile("cp.async.wait_group 0;");
        }
        __syncthreads();

        const uint32_t* Aw = reinterpret_cast<const uint32_t*>(sm + (kt & 1) * STAGE_HALVES);
        const uint32_t* Bw = Aw + TILE_HALVES / 2;

#pragma unroll
        for (int ks = 0; ks < 4; ks++) {       // 4 ksteps of k16 per BK=64
            const int kw = ks * 8;             // word offset
            uint32_t af[4][4];
#pragma unroll
            for (int mt = 0; mt < 4; mt++) {
                const uint32_t* ap = Aw + (wm * 64 + mt * 16) * (LDT / 2) + kw;
                af[mt][0] = ap[(g    ) * (LDT / 2) + t    ];
                af[mt][1] = ap[(g + 8) * (LDT / 2) + t    ];
                af[mt][2] = ap[(g    ) * (LDT / 2) + t + 4];
                af[mt][3] = ap[(g + 8) * (LDT / 2) + t + 4];
            }
            uint32_t bf[8][2];
#pragma unroll
            for (int nt = 0; nt < 8; nt++) {
                const uint32_t* bp = Bw + (wn * 64 + nt * 8 + g) * (LDT / 2) + kw;
                bf[nt][0] = bp[t];
                bf[nt][1] = bp[t + 4];
            }
#pragma unroll
            for (int mt = 0; mt < 4; mt++)
#pragma unroll
                for (int nt = 0; nt < 8; nt++)
                    mma_bf16(acc[mt][nt], af[mt], bf[nt]);
        }
        __syncthreads();
    }

    // --- epilogue: per-thread column max over valid rows, shuffle-reduce over g ---
    float cmax[8][2];
#pragma unroll
    for (int nt = 0; nt < 8; nt++) { cmax[nt][0] = -CUDART_INF_F; cmax[nt][1] = -CUDART_INF_F; }

#pragma unroll
    for (int mt = 0; mt < 4; mt++) {
        int r0 = m0 + wm * 64 + mt * 16 + g;
        bool v0 = r0 < (SEQL - 1);
        bool v1 = (r0 + 8) < (SEQL - 1);
#pragma unroll
        for (int nt = 0; nt < 8; nt++) {
            if (v0) {
                cmax[nt][0] = fmaxf(cmax[nt][0], acc[mt][nt][0]);
                cmax[nt][1] = fmaxf(cmax[nt][1], acc[mt][nt][1]);
            }
            if (v1) {
                cmax[nt][0] = fmaxf(cmax[nt][0], acc[mt][nt][2]);
                cmax[nt][1] = fmaxf(cmax[nt][1], acc[mt][nt][3]);
            }
        }
    }
#pragma unroll
    for (int nt = 0; nt < 8; nt++)
#pragma unroll
        for (int j = 0; j < 2; j++) {
            float v = cmax[nt][j];
            v = fmaxf(v, __shfl_xor_sync(0xffffffffu, v, 4));
            v = fmaxf(v, __shfl_xor_sync(0xffffffffu, v, 8));
            v = fmaxf(v, __shfl_xor_sync(0xffffffffu, v, 16));
            cmax[nt][j] = v;
        }
    if (g == 0) {   // lanes 0..3 (lane == t)
#pragma unroll
        for (int nt = 0; nt < 8; nt++)
#pragma unroll
            for (int j = 0; j < 2; j++) {
                int col = n0 + wn * 64 + nt * 8 + 2 * t + j;
                atomicMaxFloat(&g_sentpre[(size_t)b * SDIM + col],
                               cmax[nt][j] + __ldg(&bc[col]));
            }
    }
}

// ---------------------------------------------------------------------------
// Kernel 3: fused classifier. sigmoid -> h (S->50) -> logits -> log_softmax.
// Grid 64 (one block per batch), 256 threads.
// ---------------------------------------------------------------------------
__global__ __launch_bounds__(256) void cls_kernel(
    const float* __restrict__ W1, const float* __restrict__ b1,
    const float* __restrict__ W2, const float* __restrict__ b2,
    float* __restrict__ out)
{
    const int b = blockIdx.x;
    __shared__ float sent[SDIM];
    __shared__ float h[64];

    for (int i = threadIdx.x; i < SDIM; i += 256) {
        float v = g_sentpre[(size_t)b * SDIM + i];
        sent[i] = 1.0f / (1.0f + expf(-v));
    }
    __syncthreads();

    const int w    = threadIdx.x >> 5;
    const int lane = threadIdx.x & 31;
    for (int j = w; j < 50; j += 8) {
        const float4* wrow = reinterpret_cast<const float4*>(W1 + (size_t)j * SDIM);
        float sum = 0.0f;
#pragma unroll
        for (int i = lane; i < SDIM / 4; i += 32) {
            float4 v = wrow[i];
            const float* s = &sent[i * 4];
            sum = fmaf(v.x, s[0], sum);
            sum = fmaf(v.y, s[1], sum);
            sum = fmaf(v.z, s[2], sum);
            sum = fmaf(v.w, s[3], sum);
        }
#pragma unroll
        for (int o = 16; o > 0; o >>= 1) sum += __shfl_down_sync(0xffffffffu, sum, o);
        if (lane == 0) h[j] = sum + b1[j];
    }
    __syncthreads();

    if (threadIdx.x == 0) {
        float l0 = b2[0], l1 = b2[1];
#pragma unroll
        for (int j = 0; j < 50; j++) {
            l0 = fmaf(h[j], W2[j], l0);
            l1 = fmaf(h[j], W2[50 + j], l1);
        }
        float m   = fmaxf(l0, l1);
        float lse = m + logf(expf(l0 - m) + expf(l1 - m));
        out[b * NCLASS + 0] = l0 - lse;
        out[b * NCLASS + 1] = l1 - lse;
    }
}

// ---------------------------------------------------------------------------
// kernel_launch
// inputs order: inputs(int32), emb_table, Wc, bc, W1, b1, W2, b2
// ---------------------------------------------------------------------------
extern "C" void kernel_launch(void* const* d_in, const int* in_sizes, int n_in,
                              void* d_out, int out_size) {
    const int*   inputs = (const int*)  d_in[0];
    const float* emb    = (const float*)d_in[1];
    const float* Wc     = (const float*)d_in[2];
    const float* bc     = (const float*)d_in[3];
    const float* W1     = (const float*)d_in[4];
    const float* b1     = (const float*)d_in[5];
    const float* W2     = (const float*)d_in[6];
    const float* b2     = (const float*)d_in[7];
    float* out = (float*)d_out;

    cudaFuncSetAttribute(conv_max_kernel,
                         cudaFuncAttributeMaxDynamicSharedMemorySize, SMEM_BYTES);

    gather_kernel<<<BATCH * SEQL, 128>>>(inputs, emb);
    wc_round_kernel<<<(SDIM * KDIM / 4) / 256, 256>>>(Wc);   // also inits g_sentpre

    dim3 grid(SDIM / BN, (SEQL + BM - 1) / BM, BATCH);   // (8, 2, 64)
    conv_max_kernel<<<grid, 128, SMEM_BYTES>>>(bc);

    cls_kernel<<<BATCH, 256>>>(W1, b1, W2, b2, out);
}

// round 11
// speedup vs baseline: 2.2931x; 1.0300x over previous
#include <cuda_runtime.h>
#include <cuda_bf16.h>
#include <math_constants.h>
#include <cstdint>

// Problem constants
#define BATCH   64
#define SEQL    256
#define EDIM    512
#define SDIM    1024
#define KDIM    1024   // 2*E
#define NCLASS  2

// GEMM tile config (bf16 mma.sync m16n8k16) — proven 106.5us config
#define BM 128
#define BN 128
#define BK 64
#define LDT 72
#define TILE_HALVES (128 * LDT)
#define TILE_BYTES  (TILE_HALVES * 2)
#define STAGE_HALVES (2 * TILE_HALVES)
#define SMEM_BYTES (2 * STAGE_HALVES * 2)    // 73728
#define NKT (KDIM / BK)

// Scratch (static device globals)
__device__ __nv_bfloat16 g_embs[BATCH * SEQL * EDIM];
__device__ __nv_bfloat16 g_wc[SDIM * KDIM];
__device__ float g_sentpre[BATCH * SDIM];

__device__ __forceinline__ void atomicMaxFloat(float* addr, float val) {
    if (val >= 0.0f) atomicMax(reinterpret_cast<int*>(addr), __float_as_int(val));
    else             atomicMin(reinterpret_cast<unsigned int*>(addr), __float_as_uint(val));
}

__device__ __forceinline__ void mma_bf16(float c[4], const uint32_t a[4], const uint32_t b[2]) {
    asm volatile(
        "mma.sync.aligned.m16n8k16.row.col.f32.bf16.bf16.f32 "
        "{%0,%1,%2,%3}, {%4,%5,%6,%7}, {%8,%9}, {%0,%1,%2,%3};"
        : "+f"(c[0]), "+f"(c[1]), "+f"(c[2]), "+f"(c[3])
        : "r"(a[0]), "r"(a[1]), "r"(a[2]), "r"(a[3]), "r"(b[0]), "r"(b[1]));
}

__device__ __forceinline__ void cp_async16(uint32_t saddr, const void* gptr, bool pred) {
    int sz = pred ? 16 : 0;
    asm volatile("cp.async.cg.shared.global [%0], [%1], 16, %2;"
                 :: "r"(saddr), "l"(gptr), "r"(sz));
}

__device__ __forceinline__ uint32_t pack_bf16(float lo, float hi) {
    __nv_bfloat162 p = __floats2bfloat162_rn(lo, hi);
    return *reinterpret_cast<uint32_t*>(&p);
}

// ---------------------------------------------------------------------------
// Kernel 1: fused prep. Blocks [0,16384): embedding gather -> bf16.
// Blocks [16384,18432): Wc -> bf16 (128 float4 each) + sentpre init.
// ---------------------------------------------------------------------------
__global__ __launch_bounds__(128) void prep_kernel(const int* __restrict__ inputs,
                                                   const float* __restrict__ emb_table,
                                                   const float* __restrict__ Wc) {
    int bid = blockIdx.x;
    if (bid < BATCH * SEQL) {
        int tok = inputs[bid];
        float4 v = reinterpret_cast<const float4*>(emb_table + (size_t)tok * EDIM)[threadIdx.x];
        uint2 o;
        o.x = pack_bf16(v.x, v.y);
        o.y = pack_bf16(v.z, v.w);
        reinterpret_cast<uint2*>(g_embs + (size_t)bid * EDIM)[threadIdx.x] = o;
    } else {
        int wb = bid - BATCH * SEQL;          // 0..2047
        int i  = wb * 128 + threadIdx.x;      // float4 index, 262144 total
        float4 v = reinterpret_cast<const float4*>(Wc)[i];
        uint2 o;
        o.x = pack_bf16(v.x, v.y);
        o.y = pack_bf16(v.z, v.w);
        reinterpret_cast<uint2*>(g_wc)[i] = o;
        if (threadIdx.x < 32)
            g_sentpre[wb * 32 + threadIdx.x] = -CUDART_INF_F;
    }
}

// ---------------------------------------------------------------------------
// Kernel 2: BF16 tensor-core conv GEMM + fused max-pool (golden R6/R9 version).
// ---------------------------------------------------------------------------
__global__ __launch_bounds__(128, 2) void conv_max_kernel(const float* __restrict__ bc)
{
    extern __shared__ __nv_bfloat16 sm[];

    const int b   = blockIdx.z;
    const int m0  = blockIdx.y * BM;
    const int n0  = blockIdx.x * BN;
    const int tid = threadIdx.x;
    const int lane = tid & 31;
    const int warp = tid >> 5;
    const int wm = warp >> 1;
    const int wn = warp & 1;
    const int g  = lane >> 2;
    const int t  = lane & 3;

    const __nv_bfloat16* Ag = g_embs + (size_t)b * SEQL * EDIM + (size_t)m0 * EDIM;
    const __nv_bfloat16* Bg = g_wc + (size_t)n0 * KDIM;

    const uint32_t smem_u32 = (uint32_t)__cvta_generic_to_shared(sm);

    auto load_tile = [&](int kt, int st) {
        uint32_t base = smem_u32 + (uint32_t)st * (STAGE_HALVES * 2);
#pragma unroll
        for (int i = 0; i < 16; i++) {
            int c   = tid + 128 * i;
            int row = (c & 1023) >> 3;
            int ch  = c & 7;
            uint32_t daddr = base + (c < 1024 ? 0u : (uint32_t)TILE_BYTES)
                           + (uint32_t)(row * LDT * 2 + ch * 16);
            if (c < 1024) {
                bool av = (m0 + row) < (SEQL - 1);
                cp_async16(daddr, Ag + (size_t)row * EDIM + kt * BK + ch * 8, av);
            } else {
                cp_async16(daddr, Bg + (size_t)row * KDIM + kt * BK + ch * 8, true);
            }
        }
    };

    float acc[4][8][4];
#pragma unroll
    for (int mt = 0; mt < 4; mt++)
#pragma unroll
        for (int nt = 0; nt < 8; nt++)
#pragma unroll
            for (int q = 0; q < 4; q++) acc[mt][nt][q] = 0.0f;

    load_tile(0, 0);
    asm volatile("cp.async.commit_group;");

    for (int kt = 0; kt < NKT; ++kt) {
        if (kt + 1 < NKT) {
            load_tile(kt + 1, (kt + 1) & 1);
            asm volatile("cp.async.commit_group;");
            asm volatile("cp.async.wait_group 1;");
        } else {
            asm volatile("cp.async.wait_group 0;");
        }
        __syncthreads();

        const uint32_t* Aw = reinterpret_cast<const uint32_t*>(sm + (kt & 1) * STAGE_HALVES);
        const uint32_t* Bw = Aw + TILE_HALVES / 2;

#pragma unroll
        for (int ks = 0; ks < 4; ks++) {
            const int kw = ks * 8;
            uint32_t af[4][4];
#pragma unroll
            for (int mt = 0; mt < 4; mt++) {
                const uint32_t* ap = Aw + (wm * 64 + mt * 16) * (LDT / 2) + kw;
                af[mt][0] = ap[(g    ) * (LDT / 2) + t    ];
                af[mt][1] = ap[(g + 8) * (LDT / 2) + t    ];
                af[mt][2] = ap[(g    ) * (LDT / 2) + t + 4];
                af[mt][3] = ap[(g + 8) * (LDT / 2) + t + 4];
            }
            uint32_t bf[8][2];
#pragma unroll
            for (int nt = 0; nt < 8; nt++) {
                const uint32_t* bp = Bw + (wn * 64 + nt * 8 + g) * (LDT / 2) + kw;
                bf[nt][0] = bp[t];
                bf[nt][1] = bp[t + 4];
            }
#pragma unroll
            for (int mt = 0; mt < 4; mt++)
#pragma unroll
                for (int nt = 0; nt < 8; nt++)
                    mma_bf16(acc[mt][nt], af[mt], bf[nt]);
        }
        __syncthreads();
    }

    float cmax[8][2];
#pragma unroll
    for (int nt = 0; nt < 8; nt++) { cmax[nt][0] = -CUDART_INF_F; cmax[nt][1] = -CUDART_INF_F; }

#pragma unroll
    for (int mt = 0; mt < 4; mt++) {
        int r0 = m0 + wm * 64 + mt * 16 + g;
        bool v0 = r0 < (SEQL - 1);
        bool v1 = (r0 + 8) < (SEQL - 1);
#pragma unroll
        for (int nt = 0; nt < 8; nt++) {
            if (v0) {
                cmax[nt][0] = fmaxf(cmax[nt][0], acc[mt][nt][0]);
                cmax[nt][1] = fmaxf(cmax[nt][1], acc[mt][nt][1]);
            }
            if (v1) {
                cmax[nt][0] = fmaxf(cmax[nt][0], acc[mt][nt][2]);
                cmax[nt][1] = fmaxf(cmax[nt][1], acc[mt][nt][3]);
            }
        }
    }
#pragma unroll
    for (int nt = 0; nt < 8; nt++)
#pragma unroll
        for (int j = 0; j < 2; j++) {
            float v = cmax[nt][j];
            v = fmaxf(v, __shfl_xor_sync(0xffffffffu, v, 4));
            v = fmaxf(v, __shfl_xor_sync(0xffffffffu, v, 8));
            v = fmaxf(v, __shfl_xor_sync(0xffffffffu, v, 16));
            cmax[nt][j] = v;
        }
    if (g == 0) {
#pragma unroll
        for (int nt = 0; nt < 8; nt++)
#pragma unroll
            for (int j = 0; j < 2; j++) {
                int col = n0 + wn * 64 + nt * 8 + 2 * t + j;
                atomicMaxFloat(&g_sentpre[(size_t)b * SDIM + col],
                               cmax[nt][j] + __ldg(&bc[col]));
            }
    }
}

// ---------------------------------------------------------------------------
// Kernel 3: fused classifier, 1024 threads (32 warps) per batch.
// sigmoid: 1 elem/thread. h: warp w owns j=w and j=w+32 (2 short dot chains).
// ---------------------------------------------------------------------------
__global__ __launch_bounds__(1024) void cls_kernel(
    const float* __restrict__ W1, const float* __restrict__ b1,
    const float* __restrict__ W2, const float* __restrict__ b2,
    float* __restrict__ out)
{
    const int b = blockIdx.x;
    __shared__ float sent[SDIM];
    __shared__ float h[64];

    {
        float v = g_sentpre[(size_t)b * SDIM + threadIdx.x];
        sent[threadIdx.x] = 1.0f / (1.0f + expf(-v));
    }
    __syncthreads();

    const int warp = threadIdx.x >> 5;
    const int lane = threadIdx.x & 31;
#pragma unroll
    for (int jj = 0; jj < 2; jj++) {
        int j = warp + jj * 32;
        if (j < 50) {
            const float4* wrow = reinterpret_cast<const float4*>(W1 + (size_t)j * SDIM);
            float sum = 0.0f;
#pragma unroll
            for (int q = 0; q < 8; q++) {
                int i = lane + q * 32;            // float4 index 0..255
                float4 v = wrow[i];
                const float* s = &sent[i * 4];
                sum = fmaf(v.x, s[0], sum);
                sum = fmaf(v.y, s[1], sum);
                sum = fmaf(v.z, s[2], sum);
                sum = fmaf(v.w, s[3], sum);
            }
#pragma unroll
            for (int o = 16; o > 0; o >>= 1) sum += __shfl_down_sync(0xffffffffu, sum, o);
            if (lane == 0) h[j] = sum + b1[j];
        }
    }
    __syncthreads();

    if (threadIdx.x < 32) {
        // parallel logits: lane j accumulates h[j]*W2 for j and j+32
        float p0 = 0.0f, p1 = 0.0f;
        if (threadIdx.x < 50) {
            float hv = h[threadIdx.x];
            p0 = hv * W2[threadIdx.x];
            p1 = hv * W2[50 + threadIdx.x];
        }
        int j2 = threadIdx.x + 32;
        if (j2 < 50) {
            float hv = h[j2];
            p0 = fmaf(hv, W2[j2], p0);
            p1 = fmaf(hv, W2[50 + j2], p1);
        }
#pragma unroll
        for (int o = 16; o > 0; o >>= 1) {
            p0 += __shfl_down_sync(0xffffffffu, p0, o);
            p1 += __shfl_down_sync(0xffffffffu, p1, o);
        }
        if (threadIdx.x == 0) {
            float l0 = p0 + b2[0], l1 = p1 + b2[1];
            float m   = fmaxf(l0, l1);
            float lse = m + logf(expf(l0 - m) + expf(l1 - m));
            out[b * NCLASS + 0] = l0 - lse;
            out[b * NCLASS + 1] = l1 - lse;
        }
    }
}

// ---------------------------------------------------------------------------
// kernel_launch
// inputs order: inputs(int32), emb_table, Wc, bc, W1, b1, W2, b2
// ---------------------------------------------------------------------------
extern "C" void kernel_launch(void* const* d_in, const int* in_sizes, int n_in,
                              void* d_out, int out_size) {
    const int*   inputs = (const int*)  d_in[0];
    const float* emb    = (const float*)d_in[1];
    const float* Wc     = (const float*)d_in[2];
    const float* bc     = (const float*)d_in[3];
    const float* W1     = (const float*)d_in[4];
    const float* b1     = (const float*)d_in[5];
    const float* W2     = (const float*)d_in[6];
    const float* b2     = (const float*)d_in[7];
    float* out = (float*)d_out;

    cudaFuncSetAttribute(conv_max_kernel,
                         cudaFuncAttributeMaxDynamicSharedMemorySize, SMEM_BYTES);

    prep_kernel<<<BATCH * SEQL + 2048, 128>>>(inputs, emb, Wc);

    dim3 grid(SDIM / BN, (SEQL + BM - 1) / BM, BATCH);   // (8, 2, 64)
    conv_max_kernel<<<grid, 128, SMEM_BYTES>>>(bc);

    cls_kernel<<<BATCH, 1024>>>(W1, b1, W2, b2, out);
}

// round 12
// speedup vs baseline: 2.3983x; 1.0459x over previous
#include <cuda_runtime.h>
#include <cuda_bf16.h>
#include <math_constants.h>
#include <cstdint>

// Problem constants
#define BATCH   64
#define SEQL    256
#define EDIM    512
#define SDIM    1024
#define KDIM    1024   // 2*E
#define NCLASS  2

// GEMM tile config (bf16 mma.sync m16n8k16) — proven 106.5us config
#define BM 128
#define BN 128
#define BK 64
#define LDT 72
#define TILE_HALVES (128 * LDT)
#define TILE_BYTES  (TILE_HALVES * 2)
#define STAGE_HALVES (2 * TILE_HALVES)
#define SMEM_BYTES (2 * STAGE_HALVES * 2)    // 73728
#define NKT (KDIM / BK)

// prep sizing (in float4 units)
#define N_EMB_F4 (BATCH * SEQL * EDIM / 4)            // 2,097,152
#define N_WC_F4  (SDIM * KDIM / 4)                    // 262,144
#define N_SP_F4  (BATCH * SDIM / 4)                   // 16,384
#define N_TOT_F4 (N_EMB_F4 + N_WC_F4 + N_SP_F4)       // 2,375,680
#define PREP_BLOCKS 1184
#define PREP_THREADS 256
#define PREP_ITERS 8   // 1184*256*8 = 2,424,832 >= N_TOT_F4

// Scratch (static device globals)
__device__ __nv_bfloat16 g_embs[BATCH * SEQL * EDIM];
__device__ __nv_bfloat16 g_wc[SDIM * KDIM];
__device__ float g_sentpre[BATCH * SDIM];

__device__ __forceinline__ void atomicMaxFloat(float* addr, float val) {
    if (val >= 0.0f) atomicMax(reinterpret_cast<int*>(addr), __float_as_int(val));
    else             atomicMin(reinterpret_cast<unsigned int*>(addr), __float_as_uint(val));
}

__device__ __forceinline__ void mma_bf16(float c[4], const uint32_t a[4], const uint32_t b[2]) {
    asm volatile(
        "mma.sync.aligned.m16n8k16.row.col.f32.bf16.bf16.f32 "
        "{%0,%1,%2,%3}, {%4,%5,%6,%7}, {%8,%9}, {%0,%1,%2,%3};"
        : "+f"(c[0]), "+f"(c[1]), "+f"(c[2]), "+f"(c[3])
        : "r"(a[0]), "r"(a[1]), "r"(a[2]), "r"(a[3]), "r"(b[0]), "r"(b[1]));
}

__device__ __forceinline__ void cp_async16(uint32_t saddr, const void* gptr, bool pred) {
    int sz = pred ? 16 : 0;
    asm volatile("cp.async.cg.shared.global [%0], [%1], 16, %2;"
                 :: "r"(saddr), "l"(gptr), "r"(sz));
}

__device__ __forceinline__ uint32_t pack_bf16(float lo, float hi) {
    __nv_bfloat162 p = __floats2bfloat162_rn(lo, hi);
    return *reinterpret_cast<uint32_t*>(&p);
}

// ---------------------------------------------------------------------------
// Kernel 1: fused prep, grid-stride with 8 independent iterations per thread
// (MLP=8). Covers: emb gather->bf16, Wc->bf16, sentpre=-inf.
// ---------------------------------------------------------------------------
__global__ __launch_bounds__(PREP_THREADS) void prep_kernel(
    const int* __restrict__ inputs,
    const float* __restrict__ emb_table,
    const float* __restrict__ Wc)
{
    const int stride = PREP_BLOCKS * PREP_THREADS;
    const int base = blockIdx.x * PREP_THREADS + threadIdx.x;
#pragma unroll
    for (int q = 0; q < PREP_ITERS; q++) {
        int i = base + q * stride;
        if (i < N_EMB_F4) {
            int row = i >> 7;                  // emb row (128 f4 per row)
            int col = i & 127;
            int tok = __ldg(&inputs[row]);
            float4 v = __ldg(reinterpret_cast<const float4*>(emb_table)
                             + (size_t)tok * 128 + col);
            uint2 o;
            o.x = pack_bf16(v.x, v.y);
            o.y = pack_bf16(v.z, v.w);
            reinterpret_cast<uint2*>(g_embs)[i] = o;
        } else if (i < N_EMB_F4 + N_WC_F4) {
            int j = i - N_EMB_F4;
            float4 v = __ldg(reinterpret_cast<const float4*>(Wc) + j);
            uint2 o;
            o.x = pack_bf16(v.x, v.y);
            o.y = pack_bf16(v.z, v.w);
            reinterpret_cast<uint2*>(g_wc)[j] = o;
        } else if (i < N_TOT_F4) {
            int j = i - N_EMB_F4 - N_WC_F4;
            reinterpret_cast<float4*>(g_sentpre)[j] =
                make_float4(-CUDART_INF_F, -CUDART_INF_F, -CUDART_INF_F, -CUDART_INF_F);
        }
    }
}

// ---------------------------------------------------------------------------
// Kernel 2: BF16 tensor-core conv GEMM + fused max-pool (golden version).
// ---------------------------------------------------------------------------
__global__ __launch_bounds__(128, 2) void conv_max_kernel(const float* __restrict__ bc)
{
    extern __shared__ __nv_bfloat16 sm[];

    const int b   = blockIdx.z;
    const int m0  = blockIdx.y * BM;
    const int n0  = blockIdx.x * BN;
    const int tid = threadIdx.x;
    const int lane = tid & 31;
    const int warp = tid >> 5;
    const int wm = warp >> 1;
    const int wn = warp & 1;
    const int g  = lane >> 2;
    const int t  = lane & 3;

    const __nv_bfloat16* Ag = g_embs + (size_t)b * SEQL * EDIM + (size_t)m0 * EDIM;
    const __nv_bfloat16* Bg = g_wc + (size_t)n0 * KDIM;

    const uint32_t smem_u32 = (uint32_t)__cvta_generic_to_shared(sm);

    auto load_tile = [&](int kt, int st) {
        uint32_t base = smem_u32 + (uint32_t)st * (STAGE_HALVES * 2);
#pragma unroll
        for (int i = 0; i < 16; i++) {
            int c   = tid + 128 * i;
            int row = (c & 1023) >> 3;
            int ch  = c & 7;
            uint32_t daddr = base + (c < 1024 ? 0u : (uint32_t)TILE_BYTES)
                           + (uint32_t)(row * LDT * 2 + ch * 16);
            if (c < 1024) {
                bool av = (m0 + row) < (SEQL - 1);
                cp_async16(daddr, Ag + (size_t)row * EDIM + kt * BK + ch * 8, av);
            } else {
                cp_async16(daddr, Bg + (size_t)row * KDIM + kt * BK + ch * 8, true);
            }
        }
    };

    float acc[4][8][4];
#pragma unroll
    for (int mt = 0; mt < 4; mt++)
#pragma unroll
        for (int nt = 0; nt < 8; nt++)
#pragma unroll
            for (int q = 0; q < 4; q++) acc[mt][nt][q] = 0.0f;

    load_tile(0, 0);
    asm volatile("cp.async.commit_group;");

    for (int kt = 0; kt < NKT; ++kt) {
        if (kt + 1 < NKT) {
            load_tile(kt + 1, (kt + 1) & 1);
            asm volatile("cp.async.commit_group;");
            asm volatile("cp.async.wait_group 1;");
        } else {
            asm volatile("cp.async.wait_group 0;");
        }
        __syncthreads();

        const uint32_t* Aw = reinterpret_cast<const uint32_t*>(sm + (kt & 1) * STAGE_HALVES);
        const uint32_t* Bw = Aw + TILE_HALVES / 2;

#pragma unroll
        for (int ks = 0; ks < 4; ks++) {
            const int kw = ks * 8;
            uint32_t af[4][4];
#pragma unroll
            for (int mt = 0; mt < 4; mt++) {
                const uint32_t* ap = Aw + (wm * 64 + mt * 16) * (LDT / 2) + kw;
                af[mt][0] = ap[(g    ) * (LDT / 2) + t    ];
                af[mt][1] = ap[(g + 8) * (LDT / 2) + t    ];
                af[mt][2] = ap[(g    ) * (LDT / 2) + t + 4];
                af[mt][3] = ap[(g + 8) * (LDT / 2) + t + 4];
            }
            uint32_t bf[8][2];
#pragma unroll
            for (int nt = 0; nt < 8; nt++) {
                const uint32_t* bp = Bw + (wn * 64 + nt * 8 + g) * (LDT / 2) + kw;
                bf[nt][0] = bp[t];
                bf[nt][1] = bp[t + 4];
            }
#pragma unroll
            for (int mt = 0; mt < 4; mt++)
#pragma unroll
                for (int nt = 0; nt < 8; nt++)
                    mma_bf16(acc[mt][nt], af[mt], bf[nt]);
        }
        __syncthreads();
    }

    float cmax[8][2];
#pragma unroll
    for (int nt = 0; nt < 8; nt++) { cmax[nt][0] = -CUDART_INF_F; cmax[nt][1] = -CUDART_INF_F; }

#pragma unroll
    for (int mt = 0; mt < 4; mt++) {
        int r0 = m0 + wm * 64 + mt * 16 + g;
        bool v0 = r0 < (SEQL - 1);
        bool v1 = (r0 + 8) < (SEQL - 1);
#pragma unroll
        for (int nt = 0; nt < 8; nt++) {
            if (v0) {
                cmax[nt][0] = fmaxf(cmax[nt][0], acc[mt][nt][0]);
                cmax[nt][1] = fmaxf(cmax[nt][1], acc[mt][nt][1]);
            }
            if (v1) {
                cmax[nt][0] = fmaxf(cmax[nt][0], acc[mt][nt][2]);
                cmax[nt][1] = fmaxf(cmax[nt][1], acc[mt][nt][3]);
            }
        }
    }
#pragma unroll
    for (int nt = 0; nt < 8; nt++)
#pragma unroll
        for (int j = 0; j < 2; j++) {
            float v = cmax[nt][j];
            v = fmaxf(v, __shfl_xor_sync(0xffffffffu, v, 4));
            v = fmaxf(v, __shfl_xor_sync(0xffffffffu, v, 8));
            v = fmaxf(v, __shfl_xor_sync(0xffffffffu, v, 16));
            cmax[nt][j] = v;
        }
    if (g == 0) {
#pragma unroll
        for (int nt = 0; nt < 8; nt++)
#pragma unroll
            for (int j = 0; j < 2; j++) {
                int col = n0 + wn * 64 + nt * 8 + 2 * t + j;
                atomicMaxFloat(&g_sentpre[(size_t)b * SDIM + col],
                               cmax[nt][j] + __ldg(&bc[col]));
            }
    }
}

// ---------------------------------------------------------------------------
// Kernel 3: fused classifier, 1024 threads (32 warps) per batch.
// ---------------------------------------------------------------------------
__global__ __launch_bounds__(1024) void cls_kernel(
    const float* __restrict__ W1, const float* __restrict__ b1,
    const float* __restrict__ W2, const float* __restrict__ b2,
    float* __restrict__ out)
{
    const int b = blockIdx.x;
    __shared__ float sent[SDIM];
    __shared__ float h[64];

    {
        float v = g_sentpre[(size_t)b * SDIM + threadIdx.x];
        sent[threadIdx.x] = 1.0f / (1.0f + expf(-v));
    }
    __syncthreads();

    const int warp = threadIdx.x >> 5;
    const int lane = threadIdx.x & 31;
#pragma unroll
    for (int jj = 0; jj < 2; jj++) {
        int j = warp + jj * 32;
        if (j < 50) {
            const float4* wrow = reinterpret_cast<const float4*>(W1 + (size_t)j * SDIM);
            float sum = 0.0f;
#pragma unroll
            for (int q = 0; q < 8; q++) {
                int i = lane + q * 32;
                float4 v = wrow[i];
                const float* s = &sent[i * 4];
                sum = fmaf(v.x, s[0], sum);
                sum = fmaf(v.y, s[1], sum);
                sum = fmaf(v.z, s[2], sum);
                sum = fmaf(v.w, s[3], sum);
            }
#pragma unroll
            for (int o = 16; o > 0; o >>= 1) sum += __shfl_down_sync(0xffffffffu, sum, o);
            if (lane == 0) h[j] = sum + b1[j];
        }
    }
    __syncthreads();

    if (threadIdx.x < 32) {
        float p0 = 0.0f, p1 = 0.0f;
        if (threadIdx.x < 50) {
            float hv = h[threadIdx.x];
            p0 = hv * W2[threadIdx.x];
            p1 = hv * W2[50 + threadIdx.x];
        }
        int j2 = threadIdx.x + 32;
        if (j2 < 50) {
            float hv = h[j2];
            p0 = fmaf(hv, W2[j2], p0);
            p1 = fmaf(hv, W2[50 + j2], p1);
        }
#pragma unroll
        for (int o = 16; o > 0; o >>= 1) {
            p0 += __shfl_down_sync(0xffffffffu, p0, o);
            p1 += __shfl_down_sync(0xffffffffu, p1, o);
        }
        if (threadIdx.x == 0) {
            float l0 = p0 + b2[0], l1 = p1 + b2[1];
            float m   = fmaxf(l0, l1);
            float lse = m + logf(expf(l0 - m) + expf(l1 - m));
            out[b * NCLASS + 0] = l0 - lse;
            out[b * NCLASS + 1] = l1 - lse;
        }
    }
}

// ---------------------------------------------------------------------------
// kernel_launch
// inputs order: inputs(int32), emb_table, Wc, bc, W1, b1, W2, b2
// ---------------------------------------------------------------------------
extern "C" void kernel_launch(void* const* d_in, const int* in_sizes, int n_in,
                              void* d_out, int out_size) {
    const int*   inputs = (const int*)  d_in[0];
    const float* emb    = (const float*)d_in[1];
    const float* Wc     = (const float*)d_in[2];
    const float* bc     = (const float*)d_in[3];
    const float* W1     = (const float*)d_in[4];
    const float* b1     = (const float*)d_in[5];
    const float* W2     = (const float*)d_in[6];
    const float* b2     = (const float*)d_in[7];
    float* out = (float*)d_out;

    cudaFuncSetAttribute(conv_max_kernel,
                         cudaFuncAttributeMaxDynamicSharedMemorySize, SMEM_BYTES);

    prep_kernel<<<PREP_BLOCKS, PREP_THREADS>>>(inputs, emb, Wc);

    dim3 grid(SDIM / BN, (SEQL + BM - 1) / BM, BATCH);   // (8, 2, 64)
    conv_max_kernel<<<grid, 128, SMEM_BYTES>>>(bc);

    cls_kernel<<<BATCH, 1024>>>(W1, b1, W2, b2, out);
}